// round 14
// baseline (speedup 1.0000x reference)
#include <cuda_runtime.h>
#include <cuda_fp16.h>
#include <cstdint>

#define TT    25088
#define ED    768
#define NHEAD 12
#define HDIM  64
#define NTOK  196
#define MLPD  3072

// fp16 activations / weights, fp32 residual path. Lifetime-aliased:
//   g_y  : LN1 out -> reused as LN2 out
//   g_hh : front TT*ED halves hold attn out until proj GEMM consumes them
__device__ __half g_y  [(size_t)TT * ED];
__device__ __half g_qkv[(size_t)TT * 2304];
__device__ float  g_x1 [(size_t)TT * ED];
__device__ __half g_hh [(size_t)TT * MLPD];
__device__ __half g_wqkv [768 * 2304];
__device__ __half g_wproj[768 * 768];
__device__ __half g_w1   [768 * 3072];
__device__ __half g_w2   [3072 * 768];

__device__ __forceinline__ uint32_t smem_u32(const void* p) {
    return (uint32_t)__cvta_generic_to_shared(p);
}
__device__ __forceinline__ void ldsm4(uint32_t& r0, uint32_t& r1, uint32_t& r2, uint32_t& r3,
                                      uint32_t a) {
    asm volatile("ldmatrix.sync.aligned.m8n8.x4.shared.b16 {%0,%1,%2,%3},[%4];\n"
                 : "=r"(r0), "=r"(r1), "=r"(r2), "=r"(r3) : "r"(a));
}
__device__ __forceinline__ void ldsm4t(uint32_t& r0, uint32_t& r1, uint32_t& r2, uint32_t& r3,
                                       uint32_t a) {
    asm volatile("ldmatrix.sync.aligned.m8n8.x4.trans.shared.b16 {%0,%1,%2,%3},[%4];\n"
                 : "=r"(r0), "=r"(r1), "=r"(r2), "=r"(r3) : "r"(a));
}
__device__ __forceinline__ void mma16816(float* c, const uint32_t* a, const uint32_t* b) {
    asm volatile(
        "mma.sync.aligned.m16n8k16.row.col.f32.f16.f16.f32 "
        "{%0,%1,%2,%3},{%4,%5,%6,%7},{%8,%9},{%0,%1,%2,%3};\n"
        : "+f"(c[0]), "+f"(c[1]), "+f"(c[2]), "+f"(c[3])
        : "r"(a[0]), "r"(a[1]), "r"(a[2]), "r"(a[3]), "r"(b[0]), "r"(b[1]));
}
__device__ __forceinline__ void cpasync16(void* s, const void* g) {
    asm volatile("cp.async.cg.shared.global [%0],[%1],16;\n" ::"r"(smem_u32(s)), "l"(g));
}
__device__ __forceinline__ void cp_commit() { asm volatile("cp.async.commit_group;\n"); }
__device__ __forceinline__ void cp_wait2()  { asm volatile("cp.async.wait_group 2;\n"); }

__device__ __forceinline__ int tok_to_winrow(int t) {
    int img = t / 3136; int rem = t - img * 3136;
    int r = rem / 56, c = rem - r * 56;
    return (img * 16 + (r / 14) * 4 + (c / 14)) * NTOK + (r % 14) * 14 + (c % 14);
}
__device__ __forceinline__ int winrow_to_tok(int rr) {
    int w = rr / NTOK, p = rr - w * NTOK;
    int img = w >> 4; int wi = w & 15;
    return img * 3136 + ((wi >> 2) * 14 + p / 14) * 56 + (wi & 3) * 14 + p % 14;
}

// single-launch fp32 -> fp16 weight conversion
#define CVT_S0 (768 * 2304)
#define CVT_S1 (768 * 768)
#define CVT_S2 (768 * 3072)
#define CVT_S3 (3072 * 768)
#define CVT_TOT (CVT_S0 + CVT_S1 + CVT_S2 + CVT_S3)
__global__ void cvt_all_kernel(const float* __restrict__ s0, const float* __restrict__ s1,
                               const float* __restrict__ s2, const float* __restrict__ s3) {
    for (int i = blockIdx.x * blockDim.x + threadIdx.x; i < CVT_TOT;
         i += gridDim.x * blockDim.x) {
        if (i < CVT_S0) g_wqkv[i] = __float2half_rn(s0[i]);
        else if (i < CVT_S0 + CVT_S1) g_wproj[i - CVT_S0] = __float2half_rn(s1[i - CVT_S0]);
        else if (i < CVT_S0 + CVT_S1 + CVT_S2)
            g_w1[i - CVT_S0 - CVT_S1] = __float2half_rn(s2[i - CVT_S0 - CVT_S1]);
        else g_w2[i - CVT_S0 - CVT_S1 - CVT_S2] =
            __float2half_rn(s3[i - CVT_S0 - CVT_S1 - CVT_S2]);
    }
}

__global__ __launch_bounds__(256) void ln_kernel(const float* __restrict__ x,
                                                 const float* __restrict__ w,
                                                 const float* __restrict__ b,
                                                 __half* __restrict__ out, int permute) {
    int row = blockIdx.x;
    const float* xr = x + (size_t)row * ED;
    int t = threadIdx.x;
    float v0 = xr[t], v1 = xr[t + 256], v2 = xr[t + 512];
    float s = v0 + v1 + v2;
    float q = v0 * v0 + v1 * v1 + v2 * v2;
#pragma unroll
    for (int o = 16; o; o >>= 1) {
        s += __shfl_xor_sync(0xffffffffu, s, o);
        q += __shfl_xor_sync(0xffffffffu, q, o);
    }
    __shared__ float ss[8], sq[8], smu, srs;
    if ((t & 31) == 0) { ss[t >> 5] = s; sq[t >> 5] = q; }
    __syncthreads();
    if (t == 0) {
        float S = 0.f, Q = 0.f;
#pragma unroll
        for (int i = 0; i < 8; i++) { S += ss[i]; Q += sq[i]; }
        float mu = S * (1.f / ED);
        smu = mu; srs = rsqrtf(Q * (1.f / ED) - mu * mu + 1e-5f);
    }
    __syncthreads();
    float mu = smu, rs = srs;
    int drow = permute ? tok_to_winrow(row) : row;
    __half* o = out + (size_t)drow * ED;
    o[t]       = __float2half_rn((v0 - mu) * rs * w[t]       + b[t]);
    o[t + 256] = __float2half_rn((v1 - mu) * rs * w[t + 256] + b[t + 256]);
    o[t + 512] = __float2half_rn((v2 - mu) * rs * w[t + 512] + b[t + 512]);
}

// ---- fp16 GEMM 128x128x32, 4-stage cp.async ring, 2 CTAs/SM ----
#define BM 128
#define BN 128
#define BKT 32
#define NSTG 4
#define A_STG (BM * 40)              // halves per A stage (stride 40)
#define B_STG (BKT * 136)            // halves per B stage (stride 136)
#define STG_H (A_STG + B_STG)        // 9472 halves = 18944 B per stage
#define GEMM_SMEM (NSTG * STG_H * 2) // 75776 B
#define EPI_QKV  0
#define EPI_PROJ 1
#define EPI_MLP1 2
#define EPI_MLP2 3

template <int EPI>
__global__ __launch_bounds__(256, 2) void gemm_kernel(
    const __half* __restrict__ A, const __half* __restrict__ B,
    const float* __restrict__ bias, const float* __restrict__ res,
    float* __restrict__ outf, __half* __restrict__ outh, int M, int N, int K) {
    extern __shared__ __align__(16) __half sh[];
    int bm = blockIdx.x * BM, bn = blockIdx.y * BN;
    int tid = threadIdx.x, lane = tid & 31, wid = tid >> 5;
    int wm = (wid >> 2) * 64, wn = (wid & 3) * 32;

    float acc[4][4][4];
#pragma unroll
    for (int i = 0; i < 4; i++)
#pragma unroll
        for (int j = 0; j < 4; j++)
#pragma unroll
            for (int r = 0; r < 4; r++) acc[i][j][r] = 0.f;

    auto load_tiles = [&](int k0, int st) {
        __half* As = sh + st * STG_H;
        __half* Bs = As + A_STG;
#pragma unroll
        for (int i = 0; i < 2; i++) {
            int c = tid * 2 + i;
            int ra = c >> 2, kc = c & 3;
            cpasync16(&As[ra * 40 + kc * 8], A + (size_t)(bm + ra) * K + k0 + kc * 8);
        }
#pragma unroll
        for (int i = 0; i < 2; i++) {
            int c = tid * 2 + i;
            int kr = c >> 4, nc = c & 15;
            cpasync16(&Bs[kr * 136 + nc * 8], B + (size_t)(k0 + kr) * N + bn + nc * 8);
        }
    };

    int KT = K / BKT;
    // prime 3 stages
    for (int p = 0; p < 3; p++) { load_tiles(p * BKT, p); cp_commit(); }

    for (int kt = 0; kt < KT; kt++) {
        cp_wait2();
        __syncthreads();
        // issue next stage load BEFORE compute (always commit to keep FIFO depth exact)
        if (kt + 3 < KT) load_tiles((kt + 3) * BKT, (kt + 3) & 3);
        cp_commit();
        __half* As = sh + (kt & 3) * STG_H;
        __half* Bs = As + A_STG;
#pragma unroll
        for (int kk = 0; kk < BKT; kk += 16) {
            uint32_t af[4][4], bf[4][2];
#pragma unroll
            for (int mf = 0; mf < 4; mf++) {
                uint32_t a = smem_u32(&As[(wm + mf * 16 + (lane & 15)) * 40 +
                                          kk + (lane >> 4) * 8]);
                ldsm4(af[mf][0], af[mf][1], af[mf][2], af[mf][3], a);
            }
#pragma unroll
            for (int nf2 = 0; nf2 < 2; nf2++) {
                uint32_t r0, r1, r2, r3;
                uint32_t a = smem_u32(&Bs[(kk + ((lane >> 3) & 1) * 8 + (lane & 7)) * 136 +
                                          wn + nf2 * 16 + (lane >> 4) * 8]);
                ldsm4t(r0, r1, r2, r3, a);
                bf[nf2 * 2][0] = r0; bf[nf2 * 2][1] = r1;
                bf[nf2 * 2 + 1][0] = r2; bf[nf2 * 2 + 1][1] = r3;
            }
#pragma unroll
            for (int mf = 0; mf < 4; mf++)
#pragma unroll
                for (int nf = 0; nf < 4; nf++) mma16816(acc[mf][nf], af[mf], bf[nf]);
        }
    }

#pragma unroll
    for (int mf = 0; mf < 4; mf++)
#pragma unroll
        for (int nf = 0; nf < 4; nf++) {
            int row0 = bm + wm + mf * 16 + (lane >> 2);
            int col = bn + wn + nf * 8 + (lane & 3) * 2;
            float bi0 = bias[col], bi1 = bias[col + 1];
#pragma unroll
            for (int h = 0; h < 2; h++) {
                int row = row0 + h * 8;
                float v0 = acc[mf][nf][h * 2 + 0] + bi0;
                float v1 = acc[mf][nf][h * 2 + 1] + bi1;
                if (EPI == EPI_QKV) {
                    *reinterpret_cast<__half2*>(&outh[(size_t)row * N + col]) =
                        __floats2half2_rn(v0, v1);
                } else if (EPI == EPI_MLP1) {
                    float g0 = 0.5f * v0 * (1.f + erff(v0 * 0.70710678f));
                    float g1 = 0.5f * v1 * (1.f + erff(v1 * 0.70710678f));
                    *reinterpret_cast<__half2*>(&outh[(size_t)row * N + col]) =
                        __floats2half2_rn(g0, g1);
                } else if (EPI == EPI_PROJ) {
                    size_t o = (size_t)winrow_to_tok(row) * ED + col;
                    float2 rv = *reinterpret_cast<const float2*>(res + o);
                    *reinterpret_cast<float2*>(&outf[o]) = make_float2(rv.x + v0, rv.y + v1);
                } else {
                    size_t o = (size_t)row * ED + col;
                    float2 rv = *reinterpret_cast<const float2*>(res + o);
                    *reinterpret_cast<float2*>(&outf[o]) = make_float2(rv.x + v0, rv.y + v1);
                }
            }
        }
}

// ---------------- fused windowed attention, fp16 (unchanged) ----------------
#define QLD 72
#define PLD 264
#define OFF_K   (64 * QLD * 2)
#define OFF_V   (OFF_K + 256 * QLD * 2)
#define OFF_RH  (OFF_V + 256 * QLD * 2)
#define OFF_RW  (OFF_RH + 64 * 14 * 4)
#define OFF_RED (OFF_RW + 64 * 14 * 4)
#define OFF_RM  (OFF_RED + 64 * 8 * 4)
#define OFF_RS  (OFF_RM + 64 * 4)
#define ATT_SMEM (OFF_RS + 64 * 4)

__global__ __launch_bounds__(256) void attn_kernel(const float* __restrict__ relh_tab,
                                                   const float* __restrict__ relw_tab,
                                                   __half* __restrict__ ao) {
    extern __shared__ char smem[];
    __half* Qs = (__half*)smem;
    __half* Ks = (__half*)(smem + OFF_K);
    __half* Vs = (__half*)(smem + OFF_V);
    float* relh = (float*)(smem + OFF_RH);
    float* relw = (float*)(smem + OFF_RW);
    float* red = (float*)(smem + OFF_RED);
    float* rowmax = (float*)(smem + OFF_RM);
    float* rowsum = (float*)(smem + OFF_RS);
    __half* Ps = Ks;

    int qt = blockIdx.x, wh = blockIdx.y;
    int w = wh / NHEAD, h = wh - w * NHEAD;
    int tid = threadIdx.x, lane = tid & 31, wid = tid >> 5;
    size_t base = (size_t)w * NTOK * 2304 + h * HDIM;

    for (int c = tid; c < 512; c += 256) {
        int r = c >> 3, ch = c & 7;
        int qi = qt * 64 + r;
        uint4 val = make_uint4(0, 0, 0, 0);
        if (qi < NTOK)
            val = *reinterpret_cast<const uint4*>(&g_qkv[base + (size_t)qi * 2304 + ch * 8]);
        *reinterpret_cast<uint4*>(&Qs[r * QLD + ch * 8]) = val;
    }
    for (int c = tid; c < 2048; c += 256) {
        int r = c >> 3, ch = c & 7;
        uint4 kv = make_uint4(0, 0, 0, 0), vv = make_uint4(0, 0, 0, 0);
        if (r < NTOK) {
            kv = *reinterpret_cast<const uint4*>(&g_qkv[base + (size_t)r * 2304 + 768 + ch * 8]);
            vv = *reinterpret_cast<const uint4*>(&g_qkv[base + (size_t)r * 2304 + 1536 + ch * 8]);
        }
        *reinterpret_cast<uint4*>(&Ks[r * QLD + ch * 8]) = kv;
        *reinterpret_cast<uint4*>(&Vs[r * QLD + ch * 8]) = vv;
    }
    __syncthreads();

    for (int id = tid; id < 1792; id += 256) {
        int tab = id >= 896;
        int lid = tab ? id - 896 : id;
        int i = lid / 14, kx = lid - 14 * i;
        int qi = qt * 64 + i;
        float sum = 0.f;
        if (qi < NTOK) {
            int qh = qi / 14, qw = qi - qh * 14;
            int ridx = (tab ? qw : qh) - kx + 13;
            const float* tp = (tab ? relw_tab : relh_tab) + ridx * HDIM;
#pragma unroll 8
            for (int d = 0; d < HDIM; d++) sum += __half2float(Qs[i * QLD + d]) * tp[d];
        }
        (tab ? relw : relh)[i * 14 + kx] = sum;
    }
    __syncthreads();

    float sacc[4][4][4];
#pragma unroll
    for (int i = 0; i < 4; i++)
#pragma unroll
        for (int j = 0; j < 4; j++)
#pragma unroll
            for (int r = 0; r < 4; r++) sacc[i][j][r] = 0.f;
    int n0 = wid * 32;
#pragma unroll
    for (int kk = 0; kk < HDIM; kk += 16) {
        uint32_t af[4][4], bf[4][2];
#pragma unroll
        for (int mf = 0; mf < 4; mf++) {
            uint32_t a = smem_u32(&Qs[(mf * 16 + (lane & 15)) * QLD + kk + (lane >> 4) * 8]);
            ldsm4(af[mf][0], af[mf][1], af[mf][2], af[mf][3], a);
        }
#pragma unroll
        for (int nf2 = 0; nf2 < 2; nf2++) {
            uint32_t r0, r1, r2, r3;
            uint32_t a = smem_u32(&Ks[(n0 + nf2 * 16 + (lane >> 4) * 8 + (lane & 7)) * QLD +
                                      kk + ((lane >> 3) & 1) * 8]);
            ldsm4(r0, r1, r2, r3, a);
            bf[nf2 * 2][0] = r0; bf[nf2 * 2][1] = r1;
            bf[nf2 * 2 + 1][0] = r2; bf[nf2 * 2 + 1][1] = r3;
        }
#pragma unroll
        for (int mf = 0; mf < 4; mf++)
#pragma unroll
            for (int nf = 0; nf < 4; nf++) mma16816(sacc[mf][nf], af[mf], bf[nf]);
    }

    const float scale = 0.125f;
#pragma unroll
    for (int mf = 0; mf < 4; mf++)
#pragma unroll
        for (int nf = 0; nf < 4; nf++)
#pragma unroll
            for (int r = 0; r < 4; r++) {
                int i = mf * 16 + (lane >> 2) + (r >> 1) * 8;
                int j = n0 + nf * 8 + (lane & 3) * 2 + (r & 1);
                float s;
                if (j < NTOK) {
                    int kh = j / 14, kw = j - kh * 14;
                    s = sacc[mf][nf][r] * scale + relh[i * 14 + kh] + relw[i * 14 + kw];
                } else s = -1e30f;
                sacc[mf][nf][r] = s;
            }

#pragma unroll
    for (int mf = 0; mf < 4; mf++)
#pragma unroll
        for (int rh = 0; rh < 2; rh++) {
            float m = -1e30f;
#pragma unroll
            for (int nf = 0; nf < 4; nf++) {
                m = fmaxf(m, sacc[mf][nf][rh * 2]);
                m = fmaxf(m, sacc[mf][nf][rh * 2 + 1]);
            }
            m = fmaxf(m, __shfl_xor_sync(0xffffffffu, m, 1));
            m = fmaxf(m, __shfl_xor_sync(0xffffffffu, m, 2));
            if ((lane & 3) == 0) red[(mf * 16 + (lane >> 2) + rh * 8) * 8 + wid] = m;
        }
    __syncthreads();
    if (tid < 64) {
        float m = red[tid * 8];
#pragma unroll
        for (int k = 1; k < 8; k++) m = fmaxf(m, red[tid * 8 + k]);
        rowmax[tid] = m;
    }
    __syncthreads();

#pragma unroll
    for (int mf = 0; mf < 4; mf++)
#pragma unroll
        for (int rh = 0; rh < 2; rh++) {
            int i = mf * 16 + (lane >> 2) + rh * 8;
            float rm = rowmax[i], s = 0.f;
#pragma unroll
            for (int nf = 0; nf < 4; nf++) {
                float p0 = __expf(sacc[mf][nf][rh * 2] - rm);
                float p1 = __expf(sacc[mf][nf][rh * 2 + 1] - rm);
                s += p0 + p1;
                int j = n0 + nf * 8 + (lane & 3) * 2;
                *reinterpret_cast<__half2*>(&Ps[i * PLD + j]) = __floats2half2_rn(p0, p1);
            }
            s += __shfl_xor_sync(0xffffffffu, s, 1);
            s += __shfl_xor_sync(0xffffffffu, s, 2);
            if ((lane & 3) == 0) red[i * 8 + wid] = s;
        }
    __syncthreads();
    if (tid < 64) {
        float s = 0.f;
#pragma unroll
        for (int k = 0; k < 8; k++) s += red[tid * 8 + k];
        rowsum[tid] = s;
    }
    __syncthreads();

    float oacc[4][4];
#pragma unroll
    for (int i = 0; i < 4; i++)
#pragma unroll
        for (int r = 0; r < 4; r++) oacc[i][r] = 0.f;
    int mo = (wid & 3) * 16, nh2 = (wid >> 2) * 32;
#pragma unroll
    for (int kk = 0; kk < 256; kk += 16) {
        uint32_t af[4], bf[4][2];
        uint32_t aa = smem_u32(&Ps[(mo + (lane & 15)) * PLD + kk + (lane >> 4) * 8]);
        ldsm4(af[0], af[1], af[2], af[3], aa);
#pragma unroll
        for (int nf2 = 0; nf2 < 2; nf2++) {
            uint32_t r0, r1, r2, r3;
            uint32_t a = smem_u32(&Vs[(kk + ((lane >> 3) & 1) * 8 + (lane & 7)) * QLD +
                                      nh2 + nf2 * 16 + (lane >> 4) * 8]);
            ldsm4t(r0, r1, r2, r3, a);
            bf[nf2 * 2][0] = r0; bf[nf2 * 2][1] = r1;
            bf[nf2 * 2 + 1][0] = r2; bf[nf2 * 2 + 1][1] = r3;
        }
#pragma unroll
        for (int nf = 0; nf < 4; nf++) mma16816(oacc[nf], af, bf[nf]);
    }

#pragma unroll
    for (int nf = 0; nf < 4; nf++)
#pragma unroll
        for (int rh = 0; rh < 2; rh++) {
            int i = mo + (lane >> 2) + rh * 8;
            int qi = qt * 64 + i;
            if (qi < NTOK) {
                float inv = 1.f / rowsum[i];
                int col = nh2 + nf * 8 + (lane & 3) * 2;
                *reinterpret_cast<__half2*>(
                    &ao[(size_t)(w * NTOK + qi) * ED + h * HDIM + col]) =
                    __floats2half2_rn(oacc[nf][rh * 2] * inv, oacc[nf][rh * 2 + 1] * inv);
            }
        }
}

extern "C" void kernel_launch(void* const* d_in, const int* in_sizes, int n_in,
                              void* d_out, int out_size) {
    const float* x     = (const float*)d_in[0];
    const float* n1w   = (const float*)d_in[1];
    const float* n1b   = (const float*)d_in[2];
    const float* qkvw  = (const float*)d_in[3];
    const float* qkvb  = (const float*)d_in[4];
    const float* projw = (const float*)d_in[5];
    const float* projb = (const float*)d_in[6];
    const float* rph   = (const float*)d_in[7];
    const float* rpw   = (const float*)d_in[8];
    const float* n2w   = (const float*)d_in[9];
    const float* n2b   = (const float*)d_in[10];
    const float* w1    = (const float*)d_in[11];
    const float* b1    = (const float*)d_in[12];
    const float* w2    = (const float*)d_in[13];
    const float* b2    = (const float*)d_in[14];
    float* out = (float*)d_out;

    void *py, *pqkv, *px1, *phh, *pwq, *pwp, *pw1, *pw2;
    cudaGetSymbolAddress(&py, g_y);
    cudaGetSymbolAddress(&pqkv, g_qkv);
    cudaGetSymbolAddress(&px1, g_x1);
    cudaGetSymbolAddress(&phh, g_hh);
    cudaGetSymbolAddress(&pwq, g_wqkv);
    cudaGetSymbolAddress(&pwp, g_wproj);
    cudaGetSymbolAddress(&pw1, g_w1);
    cudaGetSymbolAddress(&pw2, g_w2);
    __half* y  = (__half*)py;
    __half* ao = (__half*)phh;  // attn out aliases front of g_hh

    cudaFuncSetAttribute(attn_kernel, cudaFuncAttributeMaxDynamicSharedMemorySize, ATT_SMEM);
    cudaFuncSetAttribute(gemm_kernel<EPI_QKV>,
                         cudaFuncAttributeMaxDynamicSharedMemorySize, GEMM_SMEM);
    cudaFuncSetAttribute(gemm_kernel<EPI_PROJ>,
                         cudaFuncAttributeMaxDynamicSharedMemorySize, GEMM_SMEM);
    cudaFuncSetAttribute(gemm_kernel<EPI_MLP1>,
                         cudaFuncAttributeMaxDynamicSharedMemorySize, GEMM_SMEM);
    cudaFuncSetAttribute(gemm_kernel<EPI_MLP2>,
                         cudaFuncAttributeMaxDynamicSharedMemorySize, GEMM_SMEM);

    cvt_all_kernel<<<512, 256>>>(qkvw, projw, w1, w2);

    ln_kernel<<<TT, 256>>>(x, n1w, n1b, y, 1);

    gemm_kernel<EPI_QKV><<<dim3(TT / BM, 2304 / BN), 256, GEMM_SMEM>>>(
        y, (__half*)pwq, qkvb, nullptr, nullptr, (__half*)pqkv, TT, 2304, 768);

    attn_kernel<<<dim3(4, 128 * NHEAD), 256, ATT_SMEM>>>(rph, rpw, ao);

    gemm_kernel<EPI_PROJ><<<dim3(TT / BM, 768 / BN), 256, GEMM_SMEM>>>(
        ao, (__half*)pwp, projb, x, (float*)px1, nullptr, TT, 768, 768);

    ln_kernel<<<TT, 256>>>((float*)px1, n2w, n2b, y, 0);

    gemm_kernel<EPI_MLP1><<<dim3(TT / BM, MLPD / BN), 256, GEMM_SMEM>>>(
        y, (__half*)pw1, b1, nullptr, nullptr, (__half*)phh, TT, MLPD, 768);

    gemm_kernel<EPI_MLP2><<<dim3(TT / BM, 768 / BN), 256, GEMM_SMEM>>>(
        (__half*)phh, (__half*)pw2, b2, (float*)px1, out, nullptr, TT, 768, MLPD);
}

// round 15
// speedup vs baseline: 1.4184x; 1.4184x over previous
#include <cuda_runtime.h>
#include <cuda_fp16.h>
#include <cstdint>

#define TT    25088
#define ED    768
#define NHEAD 12
#define HDIM  64
#define NTOK  196
#define MLPD  3072

// fp16 activations / weights, fp32 residual path. Lifetime-aliased:
//   g_y  : LN1 out -> reused as LN2 out
//   g_hh : front TT*ED halves hold attn out until proj GEMM consumes them
__device__ __half g_y  [(size_t)TT * ED];
__device__ __half g_qkv[(size_t)TT * 2304];
__device__ float  g_x1 [(size_t)TT * ED];
__device__ __half g_hh [(size_t)TT * MLPD];
__device__ __half g_wqkv [768 * 2304];
__device__ __half g_wproj[768 * 768];
__device__ __half g_w1   [768 * 3072];
__device__ __half g_w2   [3072 * 768];

__device__ __forceinline__ uint32_t smem_u32(const void* p) {
    return (uint32_t)__cvta_generic_to_shared(p);
}
__device__ __forceinline__ void ldsm4(uint32_t& r0, uint32_t& r1, uint32_t& r2, uint32_t& r3,
                                      uint32_t a) {
    asm volatile("ldmatrix.sync.aligned.m8n8.x4.shared.b16 {%0,%1,%2,%3},[%4];\n"
                 : "=r"(r0), "=r"(r1), "=r"(r2), "=r"(r3) : "r"(a));
}
__device__ __forceinline__ void ldsm4t(uint32_t& r0, uint32_t& r1, uint32_t& r2, uint32_t& r3,
                                       uint32_t a) {
    asm volatile("ldmatrix.sync.aligned.m8n8.x4.trans.shared.b16 {%0,%1,%2,%3},[%4];\n"
                 : "=r"(r0), "=r"(r1), "=r"(r2), "=r"(r3) : "r"(a));
}
__device__ __forceinline__ void mma16816(float* c, const uint32_t* a, const uint32_t* b) {
    asm volatile(
        "mma.sync.aligned.m16n8k16.row.col.f32.f16.f16.f32 "
        "{%0,%1,%2,%3},{%4,%5,%6,%7},{%8,%9},{%0,%1,%2,%3};\n"
        : "+f"(c[0]), "+f"(c[1]), "+f"(c[2]), "+f"(c[3])
        : "r"(a[0]), "r"(a[1]), "r"(a[2]), "r"(a[3]), "r"(b[0]), "r"(b[1]));
}
__device__ __forceinline__ void cpasync16(void* s, const void* g) {
    asm volatile("cp.async.cg.shared.global [%0],[%1],16;\n" ::"r"(smem_u32(s)), "l"(g));
}
__device__ __forceinline__ void cp_commit() { asm volatile("cp.async.commit_group;\n"); }
__device__ __forceinline__ void cp_wait2()  { asm volatile("cp.async.wait_group 2;\n"); }

__device__ __forceinline__ int tok_to_winrow(int t) {
    int img = t / 3136; int rem = t - img * 3136;
    int r = rem / 56, c = rem - r * 56;
    return (img * 16 + (r / 14) * 4 + (c / 14)) * NTOK + (r % 14) * 14 + (c % 14);
}
__device__ __forceinline__ int winrow_to_tok(int rr) {
    int w = rr / NTOK, p = rr - w * NTOK;
    int img = w >> 4; int wi = w & 15;
    return img * 3136 + ((wi >> 2) * 14 + p / 14) * 56 + (wi & 3) * 14 + p % 14;
}

// single-launch fp32 -> fp16 weight conversion
#define CVT_S0 (768 * 2304)
#define CVT_S1 (768 * 768)
#define CVT_S2 (768 * 3072)
#define CVT_S3 (3072 * 768)
#define CVT_TOT (CVT_S0 + CVT_S1 + CVT_S2 + CVT_S3)
__global__ void cvt_all_kernel(const float* __restrict__ s0, const float* __restrict__ s1,
                               const float* __restrict__ s2, const float* __restrict__ s3) {
    for (int i = blockIdx.x * blockDim.x + threadIdx.x; i < CVT_TOT;
         i += gridDim.x * blockDim.x) {
        if (i < CVT_S0) g_wqkv[i] = __float2half_rn(s0[i]);
        else if (i < CVT_S0 + CVT_S1) g_wproj[i - CVT_S0] = __float2half_rn(s1[i - CVT_S0]);
        else if (i < CVT_S0 + CVT_S1 + CVT_S2)
            g_w1[i - CVT_S0 - CVT_S1] = __float2half_rn(s2[i - CVT_S0 - CVT_S1]);
        else g_w2[i - CVT_S0 - CVT_S1 - CVT_S2] =
            __float2half_rn(s3[i - CVT_S0 - CVT_S1 - CVT_S2]);
    }
}

__global__ __launch_bounds__(256) void ln_kernel(const float* __restrict__ x,
                                                 const float* __restrict__ w,
                                                 const float* __restrict__ b,
                                                 __half* __restrict__ out, int permute) {
    int row = blockIdx.x;
    const float* xr = x + (size_t)row * ED;
    int t = threadIdx.x;
    float v0 = xr[t], v1 = xr[t + 256], v2 = xr[t + 512];
    float s = v0 + v1 + v2;
    float q = v0 * v0 + v1 * v1 + v2 * v2;
#pragma unroll
    for (int o = 16; o; o >>= 1) {
        s += __shfl_xor_sync(0xffffffffu, s, o);
        q += __shfl_xor_sync(0xffffffffu, q, o);
    }
    __shared__ float ss[8], sq[8], smu, srs;
    if ((t & 31) == 0) { ss[t >> 5] = s; sq[t >> 5] = q; }
    __syncthreads();
    if (t == 0) {
        float S = 0.f, Q = 0.f;
#pragma unroll
        for (int i = 0; i < 8; i++) { S += ss[i]; Q += sq[i]; }
        float mu = S * (1.f / ED);
        smu = mu; srs = rsqrtf(Q * (1.f / ED) - mu * mu + 1e-5f);
    }
    __syncthreads();
    float mu = smu, rs = srs;
    int drow = permute ? tok_to_winrow(row) : row;
    __half* o = out + (size_t)drow * ED;
    o[t]       = __float2half_rn((v0 - mu) * rs * w[t]       + b[t]);
    o[t + 256] = __float2half_rn((v1 - mu) * rs * w[t + 256] + b[t + 256]);
    o[t + 512] = __float2half_rn((v2 - mu) * rs * w[t + 512] + b[t + 512]);
}

// ---- fp16 GEMM 128x128x32, 4-stage cp.async ring, 2 CTAs/SM ----
#define BM 128
#define BN 128
#define BKT 32
#define NSTG 4
#define A_STG (BM * 40)
#define B_STG (BKT * 136)
#define STG_H (A_STG + B_STG)
#define GEMM_SMEM (NSTG * STG_H * 2)
#define EPI_QKV  0
#define EPI_PROJ 1
#define EPI_MLP1 2
#define EPI_MLP2 3

template <int EPI>
__global__ __launch_bounds__(256, 2) void gemm_kernel(
    const __half* __restrict__ A, const __half* __restrict__ B,
    const float* __restrict__ bias, const float* __restrict__ res,
    float* __restrict__ outf, __half* __restrict__ outh, int M, int N, int K) {
    extern __shared__ __align__(16) __half sh[];
    int bm = blockIdx.x * BM, bn = blockIdx.y * BN;
    int tid = threadIdx.x, lane = tid & 31, wid = tid >> 5;
    int wm = (wid >> 2) * 64, wn = (wid & 3) * 32;

    float acc[4][4][4];
#pragma unroll
    for (int i = 0; i < 4; i++)
#pragma unroll
        for (int j = 0; j < 4; j++)
#pragma unroll
            for (int r = 0; r < 4; r++) acc[i][j][r] = 0.f;

    auto load_tiles = [&](int k0, int st) {
        __half* As = sh + st * STG_H;
        __half* Bs = As + A_STG;
#pragma unroll
        for (int i = 0; i < 2; i++) {
            int c = tid * 2 + i;
            int ra = c >> 2, kc = c & 3;
            cpasync16(&As[ra * 40 + kc * 8], A + (size_t)(bm + ra) * K + k0 + kc * 8);
        }
#pragma unroll
        for (int i = 0; i < 2; i++) {
            int c = tid * 2 + i;
            int kr = c >> 4, nc = c & 15;
            cpasync16(&Bs[kr * 136 + nc * 8], B + (size_t)(k0 + kr) * N + bn + nc * 8);
        }
    };

    int KT = K / BKT;
    for (int p = 0; p < 3; p++) { load_tiles(p * BKT, p); cp_commit(); }

    for (int kt = 0; kt < KT; kt++) {
        cp_wait2();
        __syncthreads();
        if (kt + 3 < KT) load_tiles((kt + 3) * BKT, (kt + 3) & 3);
        cp_commit();
        __half* As = sh + (kt & 3) * STG_H;
        __half* Bs = As + A_STG;
#pragma unroll
        for (int kk = 0; kk < BKT; kk += 16) {
            uint32_t af[4][4], bf[4][2];
#pragma unroll
            for (int mf = 0; mf < 4; mf++) {
                uint32_t a = smem_u32(&As[(wm + mf * 16 + (lane & 15)) * 40 +
                                          kk + (lane >> 4) * 8]);
                ldsm4(af[mf][0], af[mf][1], af[mf][2], af[mf][3], a);
            }
#pragma unroll
            for (int nf2 = 0; nf2 < 2; nf2++) {
                uint32_t r0, r1, r2, r3;
                uint32_t a = smem_u32(&Bs[(kk + ((lane >> 3) & 1) * 8 + (lane & 7)) * 136 +
                                          wn + nf2 * 16 + (lane >> 4) * 8]);
                ldsm4t(r0, r1, r2, r3, a);
                bf[nf2 * 2][0] = r0; bf[nf2 * 2][1] = r1;
                bf[nf2 * 2 + 1][0] = r2; bf[nf2 * 2 + 1][1] = r3;
            }
#pragma unroll
            for (int mf = 0; mf < 4; mf++)
#pragma unroll
                for (int nf = 0; nf < 4; nf++) mma16816(acc[mf][nf], af[mf], bf[nf]);
        }
    }

#pragma unroll
    for (int mf = 0; mf < 4; mf++)
#pragma unroll
        for (int nf = 0; nf < 4; nf++) {
            int row0 = bm + wm + mf * 16 + (lane >> 2);
            int col = bn + wn + nf * 8 + (lane & 3) * 2;
            float bi0 = bias[col], bi1 = bias[col + 1];
#pragma unroll
            for (int h = 0; h < 2; h++) {
                int row = row0 + h * 8;
                float v0 = acc[mf][nf][h * 2 + 0] + bi0;
                float v1 = acc[mf][nf][h * 2 + 1] + bi1;
                if (EPI == EPI_QKV) {
                    *reinterpret_cast<__half2*>(&outh[(size_t)row * N + col]) =
                        __floats2half2_rn(v0, v1);
                } else if (EPI == EPI_MLP1) {
                    float g0 = 0.5f * v0 * (1.f + erff(v0 * 0.70710678f));
                    float g1 = 0.5f * v1 * (1.f + erff(v1 * 0.70710678f));
                    *reinterpret_cast<__half2*>(&outh[(size_t)row * N + col]) =
                        __floats2half2_rn(g0, g1);
                } else if (EPI == EPI_PROJ) {
                    size_t o = (size_t)winrow_to_tok(row) * ED + col;
                    float2 rv = *reinterpret_cast<const float2*>(res + o);
                    *reinterpret_cast<float2*>(&outf[o]) = make_float2(rv.x + v0, rv.y + v1);
                } else {
                    size_t o = (size_t)row * ED + col;
                    float2 rv = *reinterpret_cast<const float2*>(res + o);
                    *reinterpret_cast<float2*>(&outf[o]) = make_float2(rv.x + v0, rv.y + v1);
                }
            }
        }
}

// ---------------- fused windowed attention, fp16 ----------------
// rel-pos bias now computed with HMMA: Rp = Q @ tab^T, gathered in scale step
#define QLD 72
#define PLD 264
#define TSTR 72
#define OFF_K   (64 * QLD * 2)                    // 9216
#define OFF_V   (OFF_K + 256 * QLD * 2)           // 46080
#define OFF_TH  (OFF_V + 256 * QLD * 2)           // 82944
#define OFF_TW  (OFF_TH + 32 * TSTR * 2)          // 87552
#define OFF_RPH (OFF_TW + 32 * TSTR * 2)          // 92160
#define OFF_RPW (OFF_RPH + 64 * 28 * 2)           // 95744
#define OFF_RED (OFF_RPW + 64 * 28 * 2)           // 99328
#define OFF_RM  (OFF_RED + 64 * 8 * 4)            // 101376
#define OFF_RS  (OFF_RM + 64 * 4)                 // 101632
#define ATT_SMEM (OFF_RS + 64 * 4)                // 101888 -> 2 CTAs/SM

__global__ __launch_bounds__(256) void attn_kernel(const float* __restrict__ relh_tab,
                                                   const float* __restrict__ relw_tab,
                                                   __half* __restrict__ ao) {
    extern __shared__ char smem[];
    __half* Qs = (__half*)smem;
    __half* Ks = (__half*)(smem + OFF_K);
    __half* Vs = (__half*)(smem + OFF_V);
    __half* Th = (__half*)(smem + OFF_TH);
    __half* Tw = (__half*)(smem + OFF_TW);
    __half* Rph = (__half*)(smem + OFF_RPH);
    __half* Rpw = (__half*)(smem + OFF_RPW);
    float* red = (float*)(smem + OFF_RED);
    float* rowmax = (float*)(smem + OFF_RM);
    float* rowsum = (float*)(smem + OFF_RS);
    __half* Ps = Ks;

    int qt = blockIdx.x, wh = blockIdx.y;
    int w = wh / NHEAD, h = wh - w * NHEAD;
    int tid = threadIdx.x, lane = tid & 31, wid = tid >> 5;
    size_t base = (size_t)w * NTOK * 2304 + h * HDIM;

    for (int c = tid; c < 512; c += 256) {
        int r = c >> 3, ch = c & 7;
        int qi = qt * 64 + r;
        uint4 val = make_uint4(0, 0, 0, 0);
        if (qi < NTOK)
            val = *reinterpret_cast<const uint4*>(&g_qkv[base + (size_t)qi * 2304 + ch * 8]);
        *reinterpret_cast<uint4*>(&Qs[r * QLD + ch * 8]) = val;
    }
    for (int c = tid; c < 2048; c += 256) {
        int r = c >> 3, ch = c & 7;
        uint4 kv = make_uint4(0, 0, 0, 0), vv = make_uint4(0, 0, 0, 0);
        if (r < NTOK) {
            kv = *reinterpret_cast<const uint4*>(&g_qkv[base + (size_t)r * 2304 + 768 + ch * 8]);
            vv = *reinterpret_cast<const uint4*>(&g_qkv[base + (size_t)r * 2304 + 1536 + ch * 8]);
        }
        *reinterpret_cast<uint4*>(&Ks[r * QLD + ch * 8]) = kv;
        *reinterpret_cast<uint4*>(&Vs[r * QLD + ch * 8]) = vv;
    }
    // rel-pos tables -> fp16 smem, 32 rows (27 valid, rest zero)
    for (int c = tid; c < 4096; c += 256) {
        int tab = c >> 11, rem = c & 2047;
        int j = rem >> 6, d = rem & 63;
        float v = (j < 27) ? (tab ? relw_tab : relh_tab)[j * HDIM + d] : 0.f;
        (tab ? Tw : Th)[j * TSTR + d] = __float2half_rn(v);
    }
    __syncthreads();

    // Rp = Q @ tab^T via HMMA: warps 0-3 -> Rph (16 rows each), 4-7 -> Rpw
    {
        int tabsel = wid >> 2, mo4 = (wid & 3) * 16;
        __half* Tsrc = tabsel ? Tw : Th;
        __half* Rdst = tabsel ? Rpw : Rph;
        float ro[4][4];
#pragma unroll
        for (int i = 0; i < 4; i++)
#pragma unroll
            for (int r = 0; r < 4; r++) ro[i][r] = 0.f;
#pragma unroll
        for (int kk = 0; kk < HDIM; kk += 16) {
            uint32_t af[4], bf[4][2];
            uint32_t aa = smem_u32(&Qs[(mo4 + (lane & 15)) * QLD + kk + (lane >> 4) * 8]);
            ldsm4(af[0], af[1], af[2], af[3], aa);
#pragma unroll
            for (int nf2 = 0; nf2 < 2; nf2++) {
                uint32_t r0, r1, r2, r3;
                uint32_t a = smem_u32(&Tsrc[(nf2 * 16 + (lane >> 4) * 8 + (lane & 7)) * TSTR +
                                            kk + ((lane >> 3) & 1) * 8]);
                ldsm4(r0, r1, r2, r3, a);
                bf[nf2 * 2][0] = r0; bf[nf2 * 2][1] = r1;
                bf[nf2 * 2 + 1][0] = r2; bf[nf2 * 2 + 1][1] = r3;
            }
#pragma unroll
            for (int nf = 0; nf < 4; nf++) mma16816(ro[nf], af, bf[nf]);
        }
#pragma unroll
        for (int nf = 0; nf < 4; nf++)
#pragma unroll
            for (int r = 0; r < 4; r++) {
                int i = mo4 + (lane >> 2) + ((r >> 1) << 3);
                int j = nf * 8 + (lane & 3) * 2 + (r & 1);
                if (j < 28) Rdst[i * 28 + j] = __float2half_rn(ro[nf][r]);
            }
    }
    __syncthreads();

    // S = Q K^T
    float sacc[4][4][4];
#pragma unroll
    for (int i = 0; i < 4; i++)
#pragma unroll
        for (int j = 0; j < 4; j++)
#pragma unroll
            for (int r = 0; r < 4; r++) sacc[i][j][r] = 0.f;
    int n0 = wid * 32;
#pragma unroll
    for (int kk = 0; kk < HDIM; kk += 16) {
        uint32_t af[4][4], bf[4][2];
#pragma unroll
        for (int mf = 0; mf < 4; mf++) {
            uint32_t a = smem_u32(&Qs[(mf * 16 + (lane & 15)) * QLD + kk + (lane >> 4) * 8]);
            ldsm4(af[mf][0], af[mf][1], af[mf][2], af[mf][3], a);
        }
#pragma unroll
        for (int nf2 = 0; nf2 < 2; nf2++) {
            uint32_t r0, r1, r2, r3;
            uint32_t a = smem_u32(&Ks[(n0 + nf2 * 16 + (lane >> 4) * 8 + (lane & 7)) * QLD +
                                      kk + ((lane >> 3) & 1) * 8]);
            ldsm4(r0, r1, r2, r3, a);
            bf[nf2 * 2][0] = r0; bf[nf2 * 2][1] = r1;
            bf[nf2 * 2 + 1][0] = r2; bf[nf2 * 2 + 1][1] = r3;
        }
#pragma unroll
        for (int mf = 0; mf < 4; mf++)
#pragma unroll
            for (int nf = 0; nf < 4; nf++) mma16816(sacc[mf][nf], af[mf], bf[nf]);
    }

    const float scale = 0.125f;
#pragma unroll
    for (int mf = 0; mf < 4; mf++)
#pragma unroll
        for (int nf = 0; nf < 4; nf++)
#pragma unroll
            for (int r = 0; r < 4; r++) {
                int i = mf * 16 + (lane >> 2) + (r >> 1) * 8;
                int j = n0 + nf * 8 + (lane & 3) * 2 + (r & 1);
                float s;
                if (j < NTOK) {
                    int qi = qt * 64 + i;
                    float bias = 0.f;
                    if (qi < NTOK) {
                        int kh = j / 14, kw = j - kh * 14;
                        int qh = qi / 14, qw = qi - qh * 14;
                        bias = __half2float(Rph[i * 28 + qh - kh + 13]) +
                               __half2float(Rpw[i * 28 + qw - kw + 13]);
                    }
                    s = sacc[mf][nf][r] * scale + bias;
                } else s = -1e30f;
                sacc[mf][nf][r] = s;
            }

#pragma unroll
    for (int mf = 0; mf < 4; mf++)
#pragma unroll
        for (int rh = 0; rh < 2; rh++) {
            float m = -1e30f;
#pragma unroll
            for (int nf = 0; nf < 4; nf++) {
                m = fmaxf(m, sacc[mf][nf][rh * 2]);
                m = fmaxf(m, sacc[mf][nf][rh * 2 + 1]);
            }
            m = fmaxf(m, __shfl_xor_sync(0xffffffffu, m, 1));
            m = fmaxf(m, __shfl_xor_sync(0xffffffffu, m, 2));
            if ((lane & 3) == 0) red[(mf * 16 + (lane >> 2) + rh * 8) * 8 + wid] = m;
        }
    __syncthreads();
    if (tid < 64) {
        float m = red[tid * 8];
#pragma unroll
        for (int k = 1; k < 8; k++) m = fmaxf(m, red[tid * 8 + k]);
        rowmax[tid] = m;
    }
    __syncthreads();

#pragma unroll
    for (int mf = 0; mf < 4; mf++)
#pragma unroll
        for (int rh = 0; rh < 2; rh++) {
            int i = mf * 16 + (lane >> 2) + rh * 8;
            float rm = rowmax[i], s = 0.f;
#pragma unroll
            for (int nf = 0; nf < 4; nf++) {
                float p0 = __expf(sacc[mf][nf][rh * 2] - rm);
                float p1 = __expf(sacc[mf][nf][rh * 2 + 1] - rm);
                s += p0 + p1;
                int j = n0 + nf * 8 + (lane & 3) * 2;
                *reinterpret_cast<__half2*>(&Ps[i * PLD + j]) = __floats2half2_rn(p0, p1);
            }
            s += __shfl_xor_sync(0xffffffffu, s, 1);
            s += __shfl_xor_sync(0xffffffffu, s, 2);
            if ((lane & 3) == 0) red[i * 8 + wid] = s;
        }
    __syncthreads();
    if (tid < 64) {
        float s = 0.f;
#pragma unroll
        for (int k = 0; k < 8; k++) s += red[tid * 8 + k];
        rowsum[tid] = s;
    }
    __syncthreads();

    // O = P @ V
    float oacc[4][4];
#pragma unroll
    for (int i = 0; i < 4; i++)
#pragma unroll
        for (int r = 0; r < 4; r++) oacc[i][r] = 0.f;
    int mo = (wid & 3) * 16, nh2 = (wid >> 2) * 32;
#pragma unroll
    for (int kk = 0; kk < 256; kk += 16) {
        uint32_t af[4], bf[4][2];
        uint32_t aa = smem_u32(&Ps[(mo + (lane & 15)) * PLD + kk + (lane >> 4) * 8]);
        ldsm4(af[0], af[1], af[2], af[3], aa);
#pragma unroll
        for (int nf2 = 0; nf2 < 2; nf2++) {
            uint32_t r0, r1, r2, r3;
            uint32_t a = smem_u32(&Vs[(kk + ((lane >> 3) & 1) * 8 + (lane & 7)) * QLD +
                                      nh2 + nf2 * 16 + (lane >> 4) * 8]);
            ldsm4t(r0, r1, r2, r3, a);
            bf[nf2 * 2][0] = r0; bf[nf2 * 2][1] = r1;
            bf[nf2 * 2 + 1][0] = r2; bf[nf2 * 2 + 1][1] = r3;
        }
#pragma unroll
        for (int nf = 0; nf < 4; nf++) mma16816(oacc[nf], af, bf[nf]);
    }

#pragma unroll
    for (int nf = 0; nf < 4; nf++)
#pragma unroll
        for (int rh = 0; rh < 2; rh++) {
            int i = mo + (lane >> 2) + rh * 8;
            int qi = qt * 64 + i;
            if (qi < NTOK) {
                float inv = 1.f / rowsum[i];
                int col = nh2 + nf * 8 + (lane & 3) * 2;
                *reinterpret_cast<__half2*>(
                    &ao[(size_t)(w * NTOK + qi) * ED + h * HDIM + col]) =
                    __floats2half2_rn(oacc[nf][rh * 2] * inv, oacc[nf][rh * 2 + 1] * inv);
            }
        }
}

extern "C" void kernel_launch(void* const* d_in, const int* in_sizes, int n_in,
                              void* d_out, int out_size) {
    const float* x     = (const float*)d_in[0];
    const float* n1w   = (const float*)d_in[1];
    const float* n1b   = (const float*)d_in[2];
    const float* qkvw  = (const float*)d_in[3];
    const float* qkvb  = (const float*)d_in[4];
    const float* projw = (const float*)d_in[5];
    const float* projb = (const float*)d_in[6];
    const float* rph   = (const float*)d_in[7];
    const float* rpw   = (const float*)d_in[8];
    const float* n2w   = (const float*)d_in[9];
    const float* n2b   = (const float*)d_in[10];
    const float* w1    = (const float*)d_in[11];
    const float* b1    = (const float*)d_in[12];
    const float* w2    = (const float*)d_in[13];
    const float* b2    = (const float*)d_in[14];
    float* out = (float*)d_out;

    void *py, *pqkv, *px1, *phh, *pwq, *pwp, *pw1, *pw2;
    cudaGetSymbolAddress(&py, g_y);
    cudaGetSymbolAddress(&pqkv, g_qkv);
    cudaGetSymbolAddress(&px1, g_x1);
    cudaGetSymbolAddress(&phh, g_hh);
    cudaGetSymbolAddress(&pwq, g_wqkv);
    cudaGetSymbolAddress(&pwp, g_wproj);
    cudaGetSymbolAddress(&pw1, g_w1);
    cudaGetSymbolAddress(&pw2, g_w2);
    __half* y  = (__half*)py;
    __half* ao = (__half*)phh;  // attn out aliases front of g_hh

    cudaFuncSetAttribute(attn_kernel, cudaFuncAttributeMaxDynamicSharedMemorySize, ATT_SMEM);
    cudaFuncSetAttribute(gemm_kernel<EPI_QKV>,
                         cudaFuncAttributeMaxDynamicSharedMemorySize, GEMM_SMEM);
    cudaFuncSetAttribute(gemm_kernel<EPI_PROJ>,
                         cudaFuncAttributeMaxDynamicSharedMemorySize, GEMM_SMEM);
    cudaFuncSetAttribute(gemm_kernel<EPI_MLP1>,
                         cudaFuncAttributeMaxDynamicSharedMemorySize, GEMM_SMEM);
    cudaFuncSetAttribute(gemm_kernel<EPI_MLP2>,
                         cudaFuncAttributeMaxDynamicSharedMemorySize, GEMM_SMEM);

    cvt_all_kernel<<<512, 256>>>(qkvw, projw, w1, w2);

    ln_kernel<<<TT, 256>>>(x, n1w, n1b, y, 1);

    gemm_kernel<EPI_QKV><<<dim3(TT / BM, 2304 / BN), 256, GEMM_SMEM>>>(
        y, (__half*)pwq, qkvb, nullptr, nullptr, (__half*)pqkv, TT, 2304, 768);

    attn_kernel<<<dim3(4, 128 * NHEAD), 256, ATT_SMEM>>>(rph, rpw, ao);

    gemm_kernel<EPI_PROJ><<<dim3(TT / BM, 768 / BN), 256, GEMM_SMEM>>>(
        ao, (__half*)pwp, projb, x, (float*)px1, nullptr, TT, 768, 768);

    ln_kernel<<<TT, 256>>>((float*)px1, n2w, n2b, y, 0);

    gemm_kernel<EPI_MLP1><<<dim3(TT / BM, MLPD / BN), 256, GEMM_SMEM>>>(
        y, (__half*)pw1, b1, nullptr, nullptr, (__half*)phh, TT, MLPD, 768);

    gemm_kernel<EPI_MLP2><<<dim3(TT / BM, 768 / BN), 256, GEMM_SMEM>>>(
        (__half*)phh, (__half*)pw2, b2, (float*)px1, out, nullptr, TT, 768, MLPD);
}

// round 16
// speedup vs baseline: 1.7740x; 1.2507x over previous
#include <cuda_runtime.h>
#include <cuda.h>
#include <cuda_fp16.h>
#include <cstdint>

#define TT    25088
#define ED    768
#define NHEAD 12
#define HDIM  64
#define NTOK  196
#define MLPD  3072

// fp16 activations / weights, fp32 residual path. Lifetime-aliased:
//   g_y  : LN1 out -> reused as LN2 out
//   g_hh : front TT*ED halves hold attn out until proj GEMM consumes them
// weights stored TRANSPOSED [N][K] (K-major rows) for the TMA/ldmatrix B path
__device__ __half g_y  [(size_t)TT * ED];
__device__ __half g_qkv[(size_t)TT * 2304];
__device__ float  g_x1 [(size_t)TT * ED];
__device__ __half g_hh [(size_t)TT * MLPD];
__device__ __half g_wqkv [2304 * 768];
__device__ __half g_wproj[768 * 768];
__device__ __half g_w1   [3072 * 768];
__device__ __half g_w2   [768 * 3072];

__device__ __forceinline__ uint32_t smem_u32(const void* p) {
    return (uint32_t)__cvta_generic_to_shared(p);
}
__device__ __forceinline__ void ldsm4(uint32_t& r0, uint32_t& r1, uint32_t& r2, uint32_t& r3,
                                      uint32_t a) {
    asm volatile("ldmatrix.sync.aligned.m8n8.x4.shared.b16 {%0,%1,%2,%3},[%4];\n"
                 : "=r"(r0), "=r"(r1), "=r"(r2), "=r"(r3) : "r"(a));
}
__device__ __forceinline__ void ldsm4t(uint32_t& r0, uint32_t& r1, uint32_t& r2, uint32_t& r3,
                                       uint32_t a) {
    asm volatile("ldmatrix.sync.aligned.m8n8.x4.trans.shared.b16 {%0,%1,%2,%3},[%4];\n"
                 : "=r"(r0), "=r"(r1), "=r"(r2), "=r"(r3) : "r"(a));
}
__device__ __forceinline__ void mma16816(float* c, const uint32_t* a, const uint32_t* b) {
    asm volatile(
        "mma.sync.aligned.m16n8k16.row.col.f32.f16.f16.f32 "
        "{%0,%1,%2,%3},{%4,%5,%6,%7},{%8,%9},{%0,%1,%2,%3};\n"
        : "+f"(c[0]), "+f"(c[1]), "+f"(c[2]), "+f"(c[3])
        : "r"(a[0]), "r"(a[1]), "r"(a[2]), "r"(a[3]), "r"(b[0]), "r"(b[1]));
}

// ---- TMA / mbarrier (sm_90 PTX; no tcgen05) ----
#define MBARRIER_INIT(addr, cnt) \
    asm volatile("mbarrier.init.shared.b64 [%0], %1;" :: "r"((uint32_t)(addr)), "r"((uint32_t)(cnt)) : "memory")
#define MBARRIER_EXPECT_TX(addr, bytes) \
    asm volatile("mbarrier.arrive.expect_tx.shared.b64 _, [%0], %1;" :: "r"((uint32_t)(addr)), "r"((uint32_t)(bytes)) : "memory")
#define MBAR_WAIT(addr, parity) do {                                              \
    asm volatile(                                                                 \
        "{\n\t.reg .pred P1;\n\t"                                                 \
        "WL_%=:\n\t"                                                              \
        "mbarrier.try_wait.parity.acquire.cta.shared::cta.b64 P1, [%0], %1, 0x989680;\n\t" \
        "@P1 bra.uni WD_%=;\n\t"                                                  \
        "bra.uni WL_%=;\n\t"                                                      \
        "WD_%=:\n\t}"                                                             \
        :: "r"((uint32_t)(addr)), "r"((uint32_t)(parity)) : "memory");            \
} while (0)

__device__ __forceinline__ void tma_ld2d(uint32_t smem_addr, const CUtensorMap* map,
                                         int x, int y, uint32_t mbar) {
    asm volatile(
        "cp.async.bulk.tensor.2d.shared::cta.global.tile.mbarrier::complete_tx::bytes "
        "[%0], [%1, {%2, %3}], [%4];"
        :: "r"(smem_addr), "l"(map), "r"(x), "r"(y), "r"(mbar) : "memory");
}

__device__ __forceinline__ int tok_to_winrow(int t) {
    int img = t / 3136; int rem = t - img * 3136;
    int r = rem / 56, c = rem - r * 56;
    return (img * 16 + (r / 14) * 4 + (c / 14)) * NTOK + (r % 14) * 14 + (c % 14);
}
__device__ __forceinline__ int winrow_to_tok(int rr) {
    int w = rr / NTOK, p = rr - w * NTOK;
    int img = w >> 4; int wi = w & 15;
    return img * 3136 + ((wi >> 2) * 14 + p / 14) * 56 + (wi & 3) * 14 + p % 14;
}

// fp32 -> fp16 TRANSPOSED weight copy: wT[n*K+k] = h(w[k*N+n])
__global__ void cvtT_kernel(const float* __restrict__ w, __half* __restrict__ wT,
                            int K, int N) {
    int total = K * N;
    for (int i = blockIdx.x * blockDim.x + threadIdx.x; i < total;
         i += gridDim.x * blockDim.x) {
        int n = i / K, k = i - n * K;
        wT[i] = __float2half_rn(w[(size_t)k * N + n]);
    }
}

__global__ __launch_bounds__(256) void ln_kernel(const float* __restrict__ x,
                                                 const float* __restrict__ w,
                                                 const float* __restrict__ b,
                                                 __half* __restrict__ out, int permute) {
    int row = blockIdx.x;
    const float* xr = x + (size_t)row * ED;
    int t = threadIdx.x;
    float v0 = xr[t], v1 = xr[t + 256], v2 = xr[t + 512];
    float s = v0 + v1 + v2;
    float q = v0 * v0 + v1 * v1 + v2 * v2;
#pragma unroll
    for (int o = 16; o; o >>= 1) {
        s += __shfl_xor_sync(0xffffffffu, s, o);
        q += __shfl_xor_sync(0xffffffffu, q, o);
    }
    __shared__ float ss[8], sq[8], smu, srs;
    if ((t & 31) == 0) { ss[t >> 5] = s; sq[t >> 5] = q; }
    __syncthreads();
    if (t == 0) {
        float S = 0.f, Q = 0.f;
#pragma unroll
        for (int i = 0; i < 8; i++) { S += ss[i]; Q += sq[i]; }
        float mu = S * (1.f / ED);
        smu = mu; srs = rsqrtf(Q * (1.f / ED) - mu * mu + 1e-5f);
    }
    __syncthreads();
    float mu = smu, rs = srs;
    int drow = permute ? tok_to_winrow(row) : row;
    __half* o = out + (size_t)drow * ED;
    o[t]       = __float2half_rn((v0 - mu) * rs * w[t]       + b[t]);
    o[t + 256] = __float2half_rn((v1 - mu) * rs * w[t + 256] + b[t + 256]);
    o[t + 512] = __float2half_rn((v2 - mu) * rs * w[t + 512] + b[t + 512]);
}

// ---- fp16 GEMM 128x128, K staged 64 halves via TMA, 3-stage mbarrier ring ----
#define TSTAGES 3
#define TILE_B  16384                         // 128 rows x 128B per operand stage
#define TMA_TX  (2 * TILE_B)
#define SM_A    1024
#define SM_B    (SM_A + TSTAGES * TILE_B)
#define GEMM_TMA_SMEM (SM_B + TSTAGES * TILE_B)   // 99328 B -> 2 CTAs/SM
#define EPI_QKV  0
#define EPI_PROJ 1
#define EPI_MLP1 2
#define EPI_MLP2 3

template <int EPI>
__global__ __launch_bounds__(256, 2) void gemm_tma(
    const __grid_constant__ CUtensorMap tma_a,
    const __grid_constant__ CUtensorMap tma_b,
    const float* __restrict__ bias, const float* __restrict__ res,
    float* __restrict__ outf, __half* __restrict__ outh, int N, int K) {
    extern __shared__ __align__(1024) char smem[];
    uint32_t sb = smem_u32(smem);
    int tid = threadIdx.x, lane = tid & 31, wid = tid >> 5;
    int bm = blockIdx.x * 128, bn = blockIdx.y * 128;
    int wm = (wid >> 2) * 64, wn = (wid & 3) * 32;

    if (tid == 0)
        for (int s = 0; s < TSTAGES; s++) MBARRIER_INIT(sb + s * 8, 1);
    __syncthreads();

    int KT = K >> 6;
    if (tid == 0) {
        for (int p = 0; p < TSTAGES; p++) {
            MBARRIER_EXPECT_TX(sb + p * 8, TMA_TX);
            tma_ld2d(sb + SM_A + p * TILE_B, &tma_a, p * 64, bm, sb + p * 8);
            tma_ld2d(sb + SM_B + p * TILE_B, &tma_b, p * 64, bn, sb + p * 8);
        }
    }

    float acc[4][4][4];
#pragma unroll
    for (int i = 0; i < 4; i++)
#pragma unroll
        for (int j = 0; j < 4; j++)
#pragma unroll
            for (int r = 0; r < 4; r++) acc[i][j][r] = 0.f;

    for (int kt = 0; kt < KT; kt++) {
        int s = kt % TSTAGES;
        MBAR_WAIT(sb + s * 8, (kt / TSTAGES) & 1);
        uint32_t Ab = sb + SM_A + s * TILE_B;
        uint32_t Bb = sb + SM_B + s * TILE_B;
#pragma unroll
        for (int kk = 0; kk < 64; kk += 16) {
            uint32_t af[4][4], bf[4][2];
#pragma unroll
            for (int mf = 0; mf < 4; mf++) {
                int row = wm + mf * 16 + (lane & 15);
                uint32_t bc = (uint32_t)(2 * kk + (lane >> 4) * 16) ^ ((row & 7) * 16);
                ldsm4(af[mf][0], af[mf][1], af[mf][2], af[mf][3], Ab + row * 128 + bc);
            }
#pragma unroll
            for (int nf2 = 0; nf2 < 2; nf2++) {
                int row = wn + nf2 * 16 + (lane >> 4) * 8 + (lane & 7);
                uint32_t bc = (uint32_t)(2 * kk + ((lane >> 3) & 1) * 16) ^ ((row & 7) * 16);
                uint32_t r0, r1, r2, r3;
                ldsm4(r0, r1, r2, r3, Bb + row * 128 + bc);
                bf[nf2 * 2][0] = r0; bf[nf2 * 2][1] = r1;
                bf[nf2 * 2 + 1][0] = r2; bf[nf2 * 2 + 1][1] = r3;
            }
#pragma unroll
            for (int mf = 0; mf < 4; mf++)
#pragma unroll
                for (int nf = 0; nf < 4; nf++) mma16816(acc[mf][nf], af[mf], bf[nf]);
        }
        __syncthreads();  // all threads done reading stage s
        if (tid == 0 && kt + TSTAGES < KT) {
            MBARRIER_EXPECT_TX(sb + s * 8, TMA_TX);
            tma_ld2d(sb + SM_A + s * TILE_B, &tma_a, (kt + TSTAGES) * 64, bm, sb + s * 8);
            tma_ld2d(sb + SM_B + s * TILE_B, &tma_b, (kt + TSTAGES) * 64, bn, sb + s * 8);
        }
    }

#pragma unroll
    for (int mf = 0; mf < 4; mf++)
#pragma unroll
        for (int nf = 0; nf < 4; nf++) {
            int row0 = bm + wm + mf * 16 + (lane >> 2);
            int col = bn + wn + nf * 8 + (lane & 3) * 2;
            float bi0 = bias[col], bi1 = bias[col + 1];
#pragma unroll
            for (int h = 0; h < 2; h++) {
                int row = row0 + h * 8;
                float v0 = acc[mf][nf][h * 2 + 0] + bi0;
                float v1 = acc[mf][nf][h * 2 + 1] + bi1;
                if (EPI == EPI_QKV) {
                    *reinterpret_cast<__half2*>(&outh[(size_t)row * N + col]) =
                        __floats2half2_rn(v0, v1);
                } else if (EPI == EPI_MLP1) {
                    float g0 = 0.5f * v0 * (1.f + erff(v0 * 0.70710678f));
                    float g1 = 0.5f * v1 * (1.f + erff(v1 * 0.70710678f));
                    *reinterpret_cast<__half2*>(&outh[(size_t)row * N + col]) =
                        __floats2half2_rn(g0, g1);
                } else if (EPI == EPI_PROJ) {
                    size_t o = (size_t)winrow_to_tok(row) * ED + col;
                    float2 rv = *reinterpret_cast<const float2*>(res + o);
                    *reinterpret_cast<float2*>(&outf[o]) = make_float2(rv.x + v0, rv.y + v1);
                } else {
                    size_t o = (size_t)row * ED + col;
                    float2 rv = *reinterpret_cast<const float2*>(res + o);
                    *reinterpret_cast<float2*>(&outf[o]) = make_float2(rv.x + v0, rv.y + v1);
                }
            }
        }
}

// ---------------- fused windowed attention, fp16 (HMMA rel-pos) ----------------
#define QLD 72
#define PLD 264
#define TSTR 72
#define OFF_K   (64 * QLD * 2)
#define OFF_V   (OFF_K + 256 * QLD * 2)
#define OFF_TH  (OFF_V + 256 * QLD * 2)
#define OFF_TW  (OFF_TH + 32 * TSTR * 2)
#define OFF_RPH (OFF_TW + 32 * TSTR * 2)
#define OFF_RPW (OFF_RPH + 64 * 28 * 2)
#define OFF_RED (OFF_RPW + 64 * 28 * 2)
#define OFF_RM  (OFF_RED + 64 * 8 * 4)
#define OFF_RS  (OFF_RM + 64 * 4)
#define ATT_SMEM (OFF_RS + 64 * 4)

__global__ __launch_bounds__(256) void attn_kernel(const float* __restrict__ relh_tab,
                                                   const float* __restrict__ relw_tab,
                                                   __half* __restrict__ ao) {
    extern __shared__ char smem[];
    __half* Qs = (__half*)smem;
    __half* Ks = (__half*)(smem + OFF_K);
    __half* Vs = (__half*)(smem + OFF_V);
    __half* Th = (__half*)(smem + OFF_TH);
    __half* Tw = (__half*)(smem + OFF_TW);
    __half* Rph = (__half*)(smem + OFF_RPH);
    __half* Rpw = (__half*)(smem + OFF_RPW);
    float* red = (float*)(smem + OFF_RED);
    float* rowmax = (float*)(smem + OFF_RM);
    float* rowsum = (float*)(smem + OFF_RS);
    __half* Ps = Ks;

    int qt = blockIdx.x, wh = blockIdx.y;
    int w = wh / NHEAD, h = wh - w * NHEAD;
    int tid = threadIdx.x, lane = tid & 31, wid = tid >> 5;
    size_t base = (size_t)w * NTOK * 2304 + h * HDIM;

    for (int c = tid; c < 512; c += 256) {
        int r = c >> 3, ch = c & 7;
        int qi = qt * 64 + r;
        uint4 val = make_uint4(0, 0, 0, 0);
        if (qi < NTOK)
            val = *reinterpret_cast<const uint4*>(&g_qkv[base + (size_t)qi * 2304 + ch * 8]);
        *reinterpret_cast<uint4*>(&Qs[r * QLD + ch * 8]) = val;
    }
    for (int c = tid; c < 2048; c += 256) {
        int r = c >> 3, ch = c & 7;
        uint4 kv = make_uint4(0, 0, 0, 0), vv = make_uint4(0, 0, 0, 0);
        if (r < NTOK) {
            kv = *reinterpret_cast<const uint4*>(&g_qkv[base + (size_t)r * 2304 + 768 + ch * 8]);
            vv = *reinterpret_cast<const uint4*>(&g_qkv[base + (size_t)r * 2304 + 1536 + ch * 8]);
        }
        *reinterpret_cast<uint4*>(&Ks[r * QLD + ch * 8]) = kv;
        *reinterpret_cast<uint4*>(&Vs[r * QLD + ch * 8]) = vv;
    }
    for (int c = tid; c < 4096; c += 256) {
        int tab = c >> 11, rem = c & 2047;
        int j = rem >> 6, d = rem & 63;
        float v = (j < 27) ? (tab ? relw_tab : relh_tab)[j * HDIM + d] : 0.f;
        (tab ? Tw : Th)[j * TSTR + d] = __float2half_rn(v);
    }
    __syncthreads();

    // Rp = Q @ tab^T via HMMA
    {
        int tabsel = wid >> 2, mo4 = (wid & 3) * 16;
        __half* Tsrc = tabsel ? Tw : Th;
        __half* Rdst = tabsel ? Rpw : Rph;
        float ro[4][4];
#pragma unroll
        for (int i = 0; i < 4; i++)
#pragma unroll
            for (int r = 0; r < 4; r++) ro[i][r] = 0.f;
#pragma unroll
        for (int kk = 0; kk < HDIM; kk += 16) {
            uint32_t af[4], bf[4][2];
            uint32_t aa = smem_u32(&Qs[(mo4 + (lane & 15)) * QLD + kk + (lane >> 4) * 8]);
            ldsm4(af[0], af[1], af[2], af[3], aa);
#pragma unroll
            for (int nf2 = 0; nf2 < 2; nf2++) {
                uint32_t r0, r1, r2, r3;
                uint32_t a = smem_u32(&Tsrc[(nf2 * 16 + (lane >> 4) * 8 + (lane & 7)) * TSTR +
                                            kk + ((lane >> 3) & 1) * 8]);
                ldsm4(r0, r1, r2, r3, a);
                bf[nf2 * 2][0] = r0; bf[nf2 * 2][1] = r1;
                bf[nf2 * 2 + 1][0] = r2; bf[nf2 * 2 + 1][1] = r3;
            }
#pragma unroll
            for (int nf = 0; nf < 4; nf++) mma16816(ro[nf], af, bf[nf]);
        }
#pragma unroll
        for (int nf = 0; nf < 4; nf++)
#pragma unroll
            for (int r = 0; r < 4; r++) {
                int i = mo4 + (lane >> 2) + ((r >> 1) << 3);
                int j = nf * 8 + (lane & 3) * 2 + (r & 1);
                if (j < 28) Rdst[i * 28 + j] = __float2half_rn(ro[nf][r]);
            }
    }
    __syncthreads();

    // S = Q K^T (warp 7's columns are all >= NTOK: skip its MMA work)
    float sacc[4][4][4];
#pragma unroll
    for (int i = 0; i < 4; i++)
#pragma unroll
        for (int j = 0; j < 4; j++)
#pragma unroll
            for (int r = 0; r < 4; r++) sacc[i][j][r] = 0.f;
    int n0 = wid * 32;
    if (n0 < NTOK) {
#pragma unroll
        for (int kk = 0; kk < HDIM; kk += 16) {
            uint32_t af[4][4], bf[4][2];
#pragma unroll
            for (int mf = 0; mf < 4; mf++) {
                uint32_t a = smem_u32(&Qs[(mf * 16 + (lane & 15)) * QLD + kk + (lane >> 4) * 8]);
                ldsm4(af[mf][0], af[mf][1], af[mf][2], af[mf][3], a);
            }
#pragma unroll
            for (int nf2 = 0; nf2 < 2; nf2++) {
                uint32_t r0, r1, r2, r3;
                uint32_t a = smem_u32(&Ks[(n0 + nf2 * 16 + (lane >> 4) * 8 + (lane & 7)) * QLD +
                                          kk + ((lane >> 3) & 1) * 8]);
                ldsm4(r0, r1, r2, r3, a);
                bf[nf2 * 2][0] = r0; bf[nf2 * 2][1] = r1;
                bf[nf2 * 2 + 1][0] = r2; bf[nf2 * 2 + 1][1] = r3;
            }
#pragma unroll
            for (int mf = 0; mf < 4; mf++)
#pragma unroll
                for (int nf = 0; nf < 4; nf++) mma16816(sacc[mf][nf], af[mf], bf[nf]);
        }
    }

    const float scale = 0.125f;
#pragma unroll
    for (int mf = 0; mf < 4; mf++)
#pragma unroll
        for (int nf = 0; nf < 4; nf++)
#pragma unroll
            for (int r = 0; r < 4; r++) {
                int i = mf * 16 + (lane >> 2) + (r >> 1) * 8;
                int j = n0 + nf * 8 + (lane & 3) * 2 + (r & 1);
                float s;
                if (j < NTOK) {
                    int qi = qt * 64 + i;
                    float bias = 0.f;
                    if (qi < NTOK) {
                        int kh = j / 14, kw = j - kh * 14;
                        int qh = qi / 14, qw = qi - qh * 14;
                        bias = __half2float(Rph[i * 28 + qh - kh + 13]) +
                               __half2float(Rpw[i * 28 + qw - kw + 13]);
                    }
                    s = sacc[mf][nf][r] * scale + bias;
                } else s = -1e30f;
                sacc[mf][nf][r] = s;
            }

#pragma unroll
    for (int mf = 0; mf < 4; mf++)
#pragma unroll
        for (int rh = 0; rh < 2; rh++) {
            float m = -1e30f;
#pragma unroll
            for (int nf = 0; nf < 4; nf++) {
                m = fmaxf(m, sacc[mf][nf][rh * 2]);
                m = fmaxf(m, sacc[mf][nf][rh * 2 + 1]);
            }
            m = fmaxf(m, __shfl_xor_sync(0xffffffffu, m, 1));
            m = fmaxf(m, __shfl_xor_sync(0xffffffffu, m, 2));
            if ((lane & 3) == 0) red[(mf * 16 + (lane >> 2) + rh * 8) * 8 + wid] = m;
        }
    __syncthreads();
    if (tid < 64) {
        float m = red[tid * 8];
#pragma unroll
        for (int k = 1; k < 8; k++) m = fmaxf(m, red[tid * 8 + k]);
        rowmax[tid] = m;
    }
    __syncthreads();

#pragma unroll
    for (int mf = 0; mf < 4; mf++)
#pragma unroll
        for (int rh = 0; rh < 2; rh++) {
            int i = mf * 16 + (lane >> 2) + rh * 8;
            float rm = rowmax[i], s = 0.f;
#pragma unroll
            for (int nf = 0; nf < 4; nf++) {
                float p0 = __expf(sacc[mf][nf][rh * 2] - rm);
                float p1 = __expf(sacc[mf][nf][rh * 2 + 1] - rm);
                s += p0 + p1;
                int j = n0 + nf * 8 + (lane & 3) * 2;
                *reinterpret_cast<__half2*>(&Ps[i * PLD + j]) = __floats2half2_rn(p0, p1);
            }
            s += __shfl_xor_sync(0xffffffffu, s, 1);
            s += __shfl_xor_sync(0xffffffffu, s, 2);
            if ((lane & 3) == 0) red[i * 8 + wid] = s;
        }
    __syncthreads();
    if (tid < 64) {
        float s = 0.f;
#pragma unroll
        for (int k = 0; k < 8; k++) s += red[tid * 8 + k];
        rowsum[tid] = s;
    }
    __syncthreads();

    // O = P @ V  (rows 196..207 are zero pad; 208 covers all nonzero P)
    float oacc[4][4];
#pragma unroll
    for (int i = 0; i < 4; i++)
#pragma unroll
        for (int r = 0; r < 4; r++) oacc[i][r] = 0.f;
    int mo = (wid & 3) * 16, nh2 = (wid >> 2) * 32;
#pragma unroll
    for (int kk = 0; kk < 208; kk += 16) {
        uint32_t af[4], bf[4][2];
        uint32_t aa = smem_u32(&Ps[(mo + (lane & 15)) * PLD + kk + (lane >> 4) * 8]);
        ldsm4(af[0], af[1], af[2], af[3], aa);
#pragma unroll
        for (int nf2 = 0; nf2 < 2; nf2++) {
            uint32_t r0, r1, r2, r3;
            uint32_t a = smem_u32(&Vs[(kk + ((lane >> 3) & 1) * 8 + (lane & 7)) * QLD +
                                      nh2 + nf2 * 16 + (lane >> 4) * 8]);
            ldsm4t(r0, r1, r2, r3, a);
            bf[nf2 * 2][0] = r0; bf[nf2 * 2][1] = r1;
            bf[nf2 * 2 + 1][0] = r2; bf[nf2 * 2 + 1][1] = r3;
        }
#pragma unroll
        for (int nf = 0; nf < 4; nf++) mma16816(oacc[nf], af, bf[nf]);
    }

#pragma unroll
    for (int nf = 0; nf < 4; nf++)
#pragma unroll
        for (int rh = 0; rh < 2; rh++) {
            int i = mo + (lane >> 2) + rh * 8;
            int qi = qt * 64 + i;
            if (qi < NTOK) {
                float inv = 1.f / rowsum[i];
                int col = nh2 + nf * 8 + (lane & 3) * 2;
                *reinterpret_cast<__half2*>(
                    &ao[(size_t)(w * NTOK + qi) * ED + h * HDIM + col]) =
                    __floats2half2_rn(oacc[nf][rh * 2] * inv, oacc[nf][rh * 2 + 1] * inv);
            }
        }
}

// ---------------- host ----------------
typedef CUresult (*EncodeFn)(CUtensorMap*, CUtensorMapDataType, cuuint32_t, void*,
                             const cuuint64_t*, const cuuint64_t*, const cuuint32_t*,
                             const cuuint32_t*, CUtensorMapInterleave, CUtensorMapSwizzle,
                             CUtensorMapL2promotion, CUtensorMapFloatOOBfill);

static void make_map2d(EncodeFn enc, CUtensorMap* m, void* ptr,
                       uint64_t dim0, uint64_t dim1) {
    cuuint64_t dims[2] = {dim0, dim1};
    cuuint64_t strides[1] = {dim0 * 2};
    cuuint32_t box[2] = {64, 128};   // 64 halves = 128B rows, 128 rows
    cuuint32_t es[2] = {1, 1};
    enc(m, CU_TENSOR_MAP_DATA_TYPE_FLOAT16, 2, ptr, dims, strides, box, es,
        CU_TENSOR_MAP_INTERLEAVE_NONE, CU_TENSOR_MAP_SWIZZLE_128B,
        CU_TENSOR_MAP_L2_PROMOTION_L2_128B, CU_TENSOR_MAP_FLOAT_OOB_FILL_NONE);
}

extern "C" void kernel_launch(void* const* d_in, const int* in_sizes, int n_in,
                              void* d_out, int out_size) {
    const float* x     = (const float*)d_in[0];
    const float* n1w   = (const float*)d_in[1];
    const float* n1b   = (const float*)d_in[2];
    const float* qkvw  = (const float*)d_in[3];
    const float* qkvb  = (const float*)d_in[4];
    const float* projw = (const float*)d_in[5];
    const float* projb = (const float*)d_in[6];
    const float* rph   = (const float*)d_in[7];
    const float* rpw   = (const float*)d_in[8];
    const float* n2w   = (const float*)d_in[9];
    const float* n2b   = (const float*)d_in[10];
    const float* w1    = (const float*)d_in[11];
    const float* b1    = (const float*)d_in[12];
    const float* w2    = (const float*)d_in[13];
    const float* b2    = (const float*)d_in[14];
    float* out = (float*)d_out;

    void *py, *pqkv, *px1, *phh, *pwq, *pwp, *pw1, *pw2;
    cudaGetSymbolAddress(&py, g_y);
    cudaGetSymbolAddress(&pqkv, g_qkv);
    cudaGetSymbolAddress(&px1, g_x1);
    cudaGetSymbolAddress(&phh, g_hh);
    cudaGetSymbolAddress(&pwq, g_wqkv);
    cudaGetSymbolAddress(&pwp, g_wproj);
    cudaGetSymbolAddress(&pw1, g_w1);
    cudaGetSymbolAddress(&pw2, g_w2);
    __half* y  = (__half*)py;
    __half* ao = (__half*)phh;  // attn out aliases front of g_hh

    void* encp = nullptr;
    cudaDriverEntryPointQueryResult qr;
    cudaGetDriverEntryPoint("cuTensorMapEncodeTiled", &encp, cudaEnableDefault, &qr);
    EncodeFn enc = (EncodeFn)encp;

    CUtensorMap mA_y, mA_ao, mA_hh, mB_qkv, mB_proj, mB_w1, mB_w2;
    make_map2d(enc, &mA_y,    py,  768,  TT);
    make_map2d(enc, &mA_ao,   phh, 768,  TT);
    make_map2d(enc, &mA_hh,   phh, 3072, TT);
    make_map2d(enc, &mB_qkv,  pwq, 768,  2304);
    make_map2d(enc, &mB_proj, pwp, 768,  768);
    make_map2d(enc, &mB_w1,   pw1, 768,  3072);
    make_map2d(enc, &mB_w2,   pw2, 3072, 768);

    cudaFuncSetAttribute(attn_kernel, cudaFuncAttributeMaxDynamicSharedMemorySize, ATT_SMEM);
    cudaFuncSetAttribute(gemm_tma<EPI_QKV>,
                         cudaFuncAttributeMaxDynamicSharedMemorySize, GEMM_TMA_SMEM);
    cudaFuncSetAttribute(gemm_tma<EPI_PROJ>,
                         cudaFuncAttributeMaxDynamicSharedMemorySize, GEMM_TMA_SMEM);
    cudaFuncSetAttribute(gemm_tma<EPI_MLP1>,
                         cudaFuncAttributeMaxDynamicSharedMemorySize, GEMM_TMA_SMEM);
    cudaFuncSetAttribute(gemm_tma<EPI_MLP2>,
                         cudaFuncAttributeMaxDynamicSharedMemorySize, GEMM_TMA_SMEM);

    cvtT_kernel<<<512, 256>>>(qkvw, (__half*)pwq, 768, 2304);
    cvtT_kernel<<<256, 256>>>(projw, (__half*)pwp, 768, 768);
    cvtT_kernel<<<512, 256>>>(w1, (__half*)pw1, 768, 3072);
    cvtT_kernel<<<512, 256>>>(w2, (__half*)pw2, 3072, 768);

    ln_kernel<<<TT, 256>>>(x, n1w, n1b, y, 1);

    gemm_tma<EPI_QKV><<<dim3(TT / 128, 2304 / 128), 256, GEMM_TMA_SMEM>>>(
        mA_y, mB_qkv, qkvb, nullptr, nullptr, (__half*)pqkv, 2304, 768);

    attn_kernel<<<dim3(4, 128 * NHEAD), 256, ATT_SMEM>>>(rph, rpw, ao);

    gemm_tma<EPI_PROJ><<<dim3(TT / 128, 768 / 128), 256, GEMM_TMA_SMEM>>>(
        mA_ao, mB_proj, projb, x, (float*)px1, nullptr, 768, 768);

    ln_kernel<<<TT, 256>>>((float*)px1, n2w, n2b, y, 0);

    gemm_tma<EPI_MLP1><<<dim3(TT / 128, MLPD / 128), 256, GEMM_TMA_SMEM>>>(
        mA_y, mB_w1, b1, nullptr, nullptr, (__half*)phh, MLPD, 768);

    gemm_tma<EPI_MLP2><<<dim3(TT / 128, 768 / 128), 256, GEMM_TMA_SMEM>>>(
        mA_hh, mB_w2, b2, (float*)px1, out, nullptr, 768, 3072);
}